// round 2
// baseline (speedup 1.0000x reference)
#include <cuda_runtime.h>
#include <cstdint>

typedef unsigned long long u64;

// ---------- f32x2 packed-math helpers (sm_100+) ----------
__device__ __forceinline__ void fma2(u64 &d, u64 a, u64 b) {
    asm("fma.rn.f32x2 %0, %1, %2, %0;" : "+l"(d) : "l"(a), "l"(b));
}
__device__ __forceinline__ void add2(u64 &d, u64 a) {
    asm("add.rn.f32x2 %0, %1, %0;" : "+l"(d) : "l"(a));
}
__device__ __forceinline__ u64 pk2(float lo, float hi) {
    u64 r; asm("mov.b64 %0, {%1, %2};" : "=l"(r) : "f"(lo), "f"(hi)); return r;
}
__device__ __forceinline__ void upk2(u64 v, float &lo, float &hi) {
    asm("mov.b64 {%0, %1}, %2;" : "=f"(lo), "=f"(hi) : "l"(v));
}

// key = (order-preserving uint of score) << 32 | index  (exact fp32 ordering)
__device__ __forceinline__ float key_to_score(u64 k) {
    unsigned u = (unsigned)(k >> 32);
    unsigned b = (u & 0x80000000u) ? (u ^ 0x80000000u) : ~u;
    return __uint_as_float(b);
}

// ---------- scratch (no runtime allocation allowed) ----------
__device__ float g_addr[64 * 32];          // normalized addresses [n][a]
__device__ float g_mvp[32 * 64 * 68];      // mv @ Wo^T, rows padded to 68 floats

// ---------- prep: normalize addresses + project memory values through Wo ----------
__global__ void prep_kernel(const float* __restrict__ maddr,
                            const float* __restrict__ mvals,
                            const float* __restrict__ Wo)
{
    if (blockIdx.x < 512) {
        int gid = blockIdx.x * 256 + threadIdx.x;   // [0, 131072)
        int e  = gid & 63;
        int bn = gid >> 6;                          // b*64 + n
        const float4* m4 = (const float4*)(mvals + (size_t)bn * 64);
        const float4* w4 = (const float4*)(Wo + (size_t)e * 64);
        float acc = 0.f;
        #pragma unroll
        for (int i = 0; i < 16; i++) {
            float4 m = m4[i], w = w4[i];
            acc += m.x * w.x + m.y * w.y + m.z * w.z + m.w * w.w;
        }
        g_mvp[(size_t)bn * 68 + e] = acc;
    } else {
        int n = threadIdx.x;
        if (n < 64) {
            const float* ar = maddr + n * 32;
            float ss = 0.f;
            #pragma unroll
            for (int a = 0; a < 32; a++) ss += ar[a] * ar[a];
            float inv = 1.f / fmaxf(sqrtf(ss), 1e-12f);
            #pragma unroll
            for (int a = 0; a < 32; a++) g_addr[n * 32 + a] = ar[a] * inv;
        }
    }
}

// ---------- main fused kernel: one thread per token ----------
__global__ __launch_bounds__(128) void main_kernel(const float* __restrict__ x,
                                                   const float* __restrict__ Wq,
                                                   float* __restrict__ out)
{
    __shared__ __align__(16) float wq_s[32 * 64];    // [a][d]
    __shared__ __align__(16) float addr_s[64 * 32];  // [n][a]
    __shared__ __align__(16) float mvp_s[64 * 68];   // [n][e], padded stride 68

    const int tid = threadIdx.x;
    const int b   = blockIdx.y;

    for (int i = tid; i < 2048; i += 128) wq_s[i]   = Wq[i];
    for (int i = tid; i < 2048; i += 128) addr_s[i] = g_addr[i];
    {
        const float* msrc = g_mvp + (size_t)b * (64 * 68);
        for (int i = tid; i < 64 * 68; i += 128) mvp_s[i] = msrc[i];
    }
    __syncthreads();

    const int s = blockIdx.x * 128 + tid;
    const ulonglong2* xr = (const ulonglong2*)(x + ((size_t)b * 8192 + s) * 64);
    ulonglong2 xp[16];                               // 64 floats as f32x2 pairs
    #pragma unroll
    for (int i = 0; i < 16; i++) xp[i] = xr[i];

    // ---- q projection: q[a] = sum_d x[d] * Wq[a][d] ----
    float q[32];
    float qq = 0.f;
    #pragma unroll 2
    for (int a = 0; a < 32; a++) {
        const ulonglong2* w2 = (const ulonglong2*)(wq_s + a * 64); // broadcast LDS
        u64 a0 = 0, a1 = 0, a2 = 0, a3 = 0;
        #pragma unroll
        for (int i = 0; i < 16; i += 2) {
            ulonglong2 w0 = w2[i];
            ulonglong2 w1 = w2[i + 1];
            fma2(a0, xp[i].x,     w0.x);
            fma2(a1, xp[i].y,     w0.y);
            fma2(a2, xp[i + 1].x, w1.x);
            fma2(a3, xp[i + 1].y, w1.y);
        }
        add2(a0, a1); add2(a2, a3); add2(a0, a2);
        float lo, hi; upk2(a0, lo, hi);
        float qa = lo + hi;
        q[a] = qa;
        qq += qa * qa;
    }

    u64 qp[16];
    #pragma unroll
    for (int i = 0; i < 16; i++) qp[i] = pk2(q[2 * i], q[2 * i + 1]);

    // softmax scale: addresses already normalized; fold 1/T = 4 and 1/||q||
    const float scale = 4.f * rsqrtf(fmaxf(qq, 1e-24f));

    // ---- scores (raw dots; ordering identical to normalized) + streaming top-8 ----
    u64 k0 = 0, k1 = 0, k2 = 0, k3 = 0, k4 = 0, k5 = 0, k6 = 0, k7 = 0;
    for (int n = 0; n < 64; n++) {
        const ulonglong2* ar = (const ulonglong2*)(addr_s + n * 32);
        u64 a0 = 0, a1 = 0;
        #pragma unroll
        for (int i = 0; i < 8; i += 2) {
            ulonglong2 av0 = ar[i], av1 = ar[i + 1];
            fma2(a0, qp[2 * i],     av0.x);
            fma2(a1, qp[2 * i + 1], av0.y);
            fma2(a0, qp[2 * i + 2], av1.x);
            fma2(a1, qp[2 * i + 3], av1.y);
        }
        add2(a0, a1);
        float lo, hi; upk2(a0, lo, hi);
        float sc = lo + hi;

        unsigned u = __float_as_uint(sc);
        u = ((int)u < 0) ? ~u : (u | 0x80000000u);
        u64 key = ((u64)u << 32) | (unsigned)n;
        if (key > k7) {
            k7 = key;
            u64 t;
            if (k7 > k6) { t = k6; k6 = k7; k7 = t; }
            if (k6 > k5) { t = k5; k5 = k6; k6 = t; }
            if (k5 > k4) { t = k4; k4 = k5; k5 = t; }
            if (k4 > k3) { t = k3; k3 = k4; k4 = t; }
            if (k3 > k2) { t = k2; k2 = k3; k3 = t; }
            if (k2 > k1) { t = k1; k1 = k2; k2 = t; }
            if (k1 > k0) { t = k0; k0 = k1; k1 = t; }
        }
    }

    // ---- softmax over top-8; pack (weight, index) for shuffles ----
    u64 kk[8] = { k0, k1, k2, k3, k4, k5, k6, k7 };
    float smax = key_to_score(k0) * scale;
    float ev[8];
    float esum = 0.f;
    #pragma unroll
    for (int j = 0; j < 8; j++) {
        float sj = key_to_score(kk[j]) * scale;
        float e  = __expf(sj - smax);
        ev[j] = e;
        esum += e;
    }
    float rinv = 1.0f / esum;
    float pw[8];
    #pragma unroll
    for (int j = 0; j < 8; j++) {
        float wv = ev[j] * rinv;
        unsigned pu = (__float_as_uint(wv) & 0xFFFFFFC0u) | (unsigned)(kk[j] & 63u);
        pw[j] = __uint_as_float(pu);   // weight with index in low 6 mantissa bits
    }

    // ---- warp-cooperative gather + coalesced store ----
    // lanes split the 64 output dims (2 per lane); tokens iterated within warp.
    const int lane  = tid & 31;
    const int wbase = tid & ~31;
    float2* outbase = (float2*)(out + ((size_t)b * 8192 + blockIdx.x * 128 + wbase) * 64);

    for (int t = 0; t < 32; t++) {
        u64 acc = 0;
        #pragma unroll
        for (int k = 0; k < 8; k++) {
            float pwk = __shfl_sync(0xffffffffu, pw[k], t);
            unsigned pu = __float_as_uint(pwk);
            int   n  = pu & 63;
            float wv = __uint_as_float(pu & 0xFFFFFFC0u);
            // conflict-free: float-index = n*68 + 2*lane -> lanes cover all 32 banks
            const u64* mrow = (const u64*)(mvp_s + n * 68) + lane;
            fma2(acc, *mrow, pk2(wv, wv));
        }
        float o0, o1; upk2(acc, o0, o1);
        outbase[t * 32 + lane] = make_float2(o0, o1);
    }
}

extern "C" void kernel_launch(void* const* d_in, const int* in_sizes, int n_in,
                              void* d_out, int out_size)
{
    const float* x  = (const float*)d_in[0];   // [32,8192,64]
    const float* ma = (const float*)d_in[1];   // [64,32]
    const float* mv = (const float*)d_in[2];   // [32,64,64]
    const float* Wq = (const float*)d_in[3];   // [32,64]
    const float* Wo = (const float*)d_in[4];   // [64,64]
    float* out = (float*)d_out;                // [32,8192,64]

    prep_kernel<<<513, 256>>>(ma, mv, Wo);
    main_kernel<<<dim3(64, 32), 128>>>(x, Wq, out);
}

// round 6
// speedup vs baseline: 1.2186x; 1.2186x over previous
#include <cuda_runtime.h>
#include <cstdint>

typedef unsigned long long u64;

// ---------- f32x2 packed-math helpers (sm_100+) ----------
__device__ __forceinline__ void fma2(u64 &d, u64 a, u64 b) {
    asm("fma.rn.f32x2 %0, %1, %2, %0;" : "+l"(d) : "l"(a), "l"(b));
}
__device__ __forceinline__ void add2(u64 &d, u64 a) {
    asm("add.rn.f32x2 %0, %1, %0;" : "+l"(d) : "l"(a));
}
__device__ __forceinline__ u64 pk2(float lo, float hi) {
    u64 r; asm("mov.b64 %0, {%1, %2};" : "=l"(r) : "f"(lo), "f"(hi)); return r;
}
__device__ __forceinline__ void upk2(u64 v, float &lo, float &hi) {
    asm("mov.b64 {%0, %1}, %2;" : "=f"(lo), "=f"(hi) : "l"(v));
}

// ---------- device scratch (static; allocation is forbidden) ----------
__device__ float g_addr[64 * 32];            // normalized addresses [n][a]
__device__ float g_mvp[32 * 64 * 64];        // mv @ Wo^T  [b][n][e], stride 64
__device__ float g_pw[32 * 8192 * 8];        // packed (weight | idx) per token

#define NEG_INF __int_as_float(0xff800000)

// ---------- prep: normalize addresses + project memory values through Wo ----------
__global__ void prep_kernel(const float* __restrict__ maddr,
                            const float* __restrict__ mvals,
                            const float* __restrict__ Wo)
{
    if (blockIdx.x < 512) {
        int gid = blockIdx.x * 256 + threadIdx.x;   // [0, 131072)
        int e  = gid & 63;
        int bn = gid >> 6;                          // b*64 + n
        const float4* m4 = (const float4*)(mvals + (size_t)bn * 64);
        const float4* w4 = (const float4*)(Wo + (size_t)e * 64);
        float acc = 0.f;
        #pragma unroll
        for (int i = 0; i < 16; i++) {
            float4 m = m4[i], w = w4[i];
            acc += m.x * w.x + m.y * w.y + m.z * w.z + m.w * w.w;
        }
        g_mvp[(size_t)bn * 64 + e] = acc;
    } else {
        int n = threadIdx.x;
        if (n < 64) {
            const float* ar = maddr + n * 32;
            float ss = 0.f;
            #pragma unroll
            for (int a = 0; a < 32; a++) ss += ar[a] * ar[a];
            float inv = 1.f / fmaxf(sqrtf(ss), 1e-12f);
            #pragma unroll
            for (int a = 0; a < 32; a++) g_addr[n * 32 + a] = ar[a] * inv;
        }
    }
}

// exact bubble level: (K,I) incumbent vs (sc,si) candidate.
// On tie, incumbent stays (p false) -> lower-index-first, matching lax.top_k.
#define TOPK_LEVEL(K, I)                                   \
    {                                                      \
        bool  p  = sc > (K);                               \
        float hi = fmaxf((K), sc);                         \
        float lo = fminf((K), sc);                         \
        unsigned ihi = p ? si : (I);                       \
        unsigned ilo = p ? (I) : si;                       \
        (K) = hi; sc = lo; (I) = ihi; si = ilo;            \
    }

// ---------- kernel 1: q-proj + scores + exact top-8 + softmax ----------
__global__ __launch_bounds__(128, 6)
void score_kernel(const float* __restrict__ x, const float* __restrict__ Wq)
{
    __shared__ __align__(16) float wq_s[32 * 64];    // [a][d]
    __shared__ __align__(16) float addr_s[64 * 32];  // [n][a]

    const int tid = threadIdx.x;
    const int b   = blockIdx.y;

    {
        const float4* s1 = (const float4*)Wq;
        const float4* s2 = (const float4*)g_addr;
        float4* d1 = (float4*)wq_s;
        float4* d2 = (float4*)addr_s;
        #pragma unroll
        for (int i = tid; i < 512; i += 128) { d1[i] = s1[i]; d2[i] = s2[i]; }
    }
    __syncthreads();

    const size_t tok = (size_t)b * 8192 + blockIdx.x * 128 + tid;
    const ulonglong2* xr = (const ulonglong2*)(x + tok * 64);

    // ---- q projection, x streamed in quarters ----
    float q[32];
    #pragma unroll
    for (int a = 0; a < 32; a++) q[a] = 0.f;

    for (int h = 0; h < 4; h++) {
        ulonglong2 x0 = xr[h * 4 + 0];
        ulonglong2 x1 = xr[h * 4 + 1];
        ulonglong2 x2 = xr[h * 4 + 2];
        ulonglong2 x3 = xr[h * 4 + 3];
        const ulonglong2* wp = (const ulonglong2*)(wq_s) + h * 4;
        #pragma unroll
        for (int a = 0; a < 32; a++) {
            ulonglong2 w0 = wp[0], w1 = wp[1], w2 = wp[2], w3 = wp[3];
            wp += 16;
            u64 a0 = 0, a1 = 0;
            fma2(a0, x0.x, w0.x); fma2(a1, x0.y, w0.y);
            fma2(a0, x1.x, w1.x); fma2(a1, x1.y, w1.y);
            fma2(a0, x2.x, w2.x); fma2(a1, x2.y, w2.y);
            fma2(a0, x3.x, w3.x); fma2(a1, x3.y, w3.y);
            add2(a0, a1);
            float lo, hi; upk2(a0, lo, hi);
            q[a] += lo + hi;
        }
    }

    u64 qp[16];
    float qq = 0.f;
    #pragma unroll
    for (int i = 0; i < 16; i++) {
        float q0 = q[2 * i], q1 = q[2 * i + 1];
        qq += q0 * q0 + q1 * q1;
        qp[i] = pk2(q0, q1);
    }
    const float scale = 4.f * rsqrtf(fmaxf(qq, 1e-24f));

    // ---- scores + EXACT streaming top-8 (score regs + index regs) ----
    float k0 = NEG_INF, k1 = NEG_INF, k2 = NEG_INF, k3 = NEG_INF;
    float k4 = NEG_INF, k5 = NEG_INF, k6 = NEG_INF, k7 = NEG_INF;
    unsigned i0 = 0, i1 = 0, i2 = 0, i3 = 0, i4 = 0, i5 = 0, i6 = 0, i7 = 0;

    for (int n = 0; n < 64; n += 2) {
        const ulonglong2* ar = (const ulonglong2*)(addr_s + n * 32);
        u64 a0 = 0, a1 = 0, b0 = 0, b1 = 0;
        #pragma unroll
        for (int i = 0; i < 8; i++) {
            ulonglong2 av = ar[i];
            ulonglong2 bv = ar[i + 8];
            fma2(a0, qp[2 * i],     av.x);
            fma2(a1, qp[2 * i + 1], av.y);
            fma2(b0, qp[2 * i],     bv.x);
            fma2(b1, qp[2 * i + 1], bv.y);
        }
        add2(a0, a1); add2(b0, b1);
        float la, ha, lb, hb;
        upk2(a0, la, ha); upk2(b0, lb, hb);

        {
            float sc = la + ha; unsigned si = (unsigned)n;
            TOPK_LEVEL(k0, i0); TOPK_LEVEL(k1, i1);
            TOPK_LEVEL(k2, i2); TOPK_LEVEL(k3, i3);
            TOPK_LEVEL(k4, i4); TOPK_LEVEL(k5, i5);
            TOPK_LEVEL(k6, i6); TOPK_LEVEL(k7, i7);
        }
        {
            float sc = lb + hb; unsigned si = (unsigned)(n + 1);
            TOPK_LEVEL(k0, i0); TOPK_LEVEL(k1, i1);
            TOPK_LEVEL(k2, i2); TOPK_LEVEL(k3, i3);
            TOPK_LEVEL(k4, i4); TOPK_LEVEL(k5, i5);
            TOPK_LEVEL(k6, i6); TOPK_LEVEL(k7, i7);
        }
    }

    // ---- softmax over exact top-8, pack (weight | idx) ----
    float    kk[8] = { k0, k1, k2, k3, k4, k5, k6, k7 };
    unsigned ii[8] = { i0, i1, i2, i3, i4, i5, i6, i7 };
    float ev[8];
    float esum = 0.f;
    #pragma unroll
    for (int j = 0; j < 8; j++) {
        float e = __expf((kk[j] - k0) * scale);
        ev[j] = e;
        esum += e;
    }
    float rinv = 1.0f / esum;

    float p[8];
    #pragma unroll
    for (int j = 0; j < 8; j++) {
        unsigned pu = (__float_as_uint(ev[j] * rinv) & 0xFFFFFFC0u) | ii[j];
        p[j] = __uint_as_float(pu);
    }
    float4* pwout = (float4*)(g_pw + tok * 8);
    pwout[0] = make_float4(p[0], p[1], p[2], p[3]);
    pwout[1] = make_float4(p[4], p[5], p[6], p[7]);
}

// ---------- kernel 2: warp-cooperative gather + coalesced store ----------
__global__ __launch_bounds__(256)
void gather_kernel(float* __restrict__ out)
{
    __shared__ __align__(16) float mvp_s[64 * 64];   // [n][e]

    const int tid  = threadIdx.x;
    const int b    = blockIdx.y;
    const int lane = tid & 31;

    {
        const float4* src = (const float4*)(g_mvp + (size_t)b * 4096);
        float4* dst = (float4*)mvp_s;
        #pragma unroll
        for (int i = tid; i < 1024; i += 256) dst[i] = src[i];
    }

    const int sbase = blockIdx.x * 256 + (tid & ~31);
    const size_t gbase = (size_t)b * 8192 + sbase;
    float p[8];
    {
        const float4* pp = (const float4*)(g_pw + (gbase + lane) * 8);
        float4 v0 = pp[0], v1 = pp[1];
        p[0] = v0.x; p[1] = v0.y; p[2] = v0.z; p[3] = v0.w;
        p[4] = v1.x; p[5] = v1.y; p[6] = v1.z; p[7] = v1.w;
    }
    __syncthreads();

    const float2* mv2 = (const float2*)mvp_s;
    float2* outb = (float2*)(out + gbase * 64);

    for (int t = 0; t < 32; t++) {
        float acc0 = 0.f, acc1 = 0.f;
        #pragma unroll
        for (int k = 0; k < 8; k++) {
            float wv = __shfl_sync(0xffffffffu, p[k], t);
            unsigned pu = __float_as_uint(wv);
            float2 m = mv2[((pu & 63u) << 5) + lane];   // conflict-free
            acc0 += m.x * wv;       // low 6 mantissa bits dirty: <=2^-18 rel
            acc1 += m.y * wv;
        }
        outb[t * 32 + lane] = make_float2(acc0, acc1);
    }
}

extern "C" void kernel_launch(void* const* d_in, const int* in_sizes, int n_in,
                              void* d_out, int out_size)
{
    const float* x  = (const float*)d_in[0];   // [32,8192,64]
    const float* ma = (const float*)d_in[1];   // [64,32]
    const float* mv = (const float*)d_in[2];   // [32,64,64]
    const float* Wq = (const float*)d_in[3];   // [32,64]
    const float* Wo = (const float*)d_in[4];   // [64,64]
    float* out = (float*)d_out;                // [32,8192,64]

    prep_kernel<<<513, 256>>>(ma, mv, Wo);
    score_kernel<<<dim3(64, 32), 128>>>(x, Wq);
    gather_kernel<<<dim3(32, 32), 256>>>(out);
}

// round 8
// speedup vs baseline: 1.2928x; 1.0608x over previous
#include <cuda_runtime.h>
#include <cstdint>

typedef unsigned long long u64;

// ---------- f32x2 packed-math helpers (sm_100+) ----------
__device__ __forceinline__ void fma2(u64 &d, u64 a, u64 b) {
    asm("fma.rn.f32x2 %0, %1, %2, %0;" : "+l"(d) : "l"(a), "l"(b));
}
__device__ __forceinline__ void add2(u64 &d, u64 a) {
    asm("add.rn.f32x2 %0, %1, %0;" : "+l"(d) : "l"(a));
}
__device__ __forceinline__ u64 pk2(float lo, float hi) {
    u64 r; asm("mov.b64 %0, {%1, %2};" : "=l"(r) : "f"(lo), "f"(hi)); return r;
}
__device__ __forceinline__ void upk2(u64 v, float &lo, float &hi) {
    asm("mov.b64 {%0, %1}, %2;" : "=f"(lo), "=f"(hi) : "l"(v));
}

// ---------- device scratch (static; allocation is forbidden) ----------
__device__ float g_mvp[32 * 64 * 64];        // mv @ Wo^T  [b][n][e], stride 64
__device__ float g_pw[32 * 8192 * 8];        // packed (weight | idx) per token

#define NEG_INF __int_as_float(0xff800000)

// ---------- prep: project memory values through Wo (smem-tiled) ----------
// grid 64: block bx handles batch b = bx>>1, output half eh = (bx&1)*32
__global__ __launch_bounds__(256)
void prep_kernel(const float* __restrict__ mvals, const float* __restrict__ Wo)
{
    __shared__ __align__(16) float wo_s[32 * 64];    // rows eh..eh+31
    __shared__ __align__(16) float mv_s[64 * 68];    // padded stride 68

    const int tid = threadIdx.x;
    const int b   = blockIdx.x >> 1;
    const int eh  = (blockIdx.x & 1) << 5;

    {
        const float4* wsrc = (const float4*)(Wo + (size_t)eh * 64);
        float4* wdst = (float4*)wo_s;
        #pragma unroll
        for (int i = tid; i < 512; i += 256) wdst[i] = wsrc[i];

        const float4* msrc = (const float4*)(mvals + (size_t)b * 4096);
        int r  = tid >> 2;          // row 0..63
        int qd = (tid & 3) * 4;     // float4 chunk base
        float4* mdst = (float4*)(mv_s + r * 68);
        #pragma unroll
        for (int j = 0; j < 4; j++) mdst[qd + j] = msrc[r * 16 + qd + j];
    }
    __syncthreads();

    const int n    = tid & 63;
    const int egrp = tid >> 6;                      // 0..3 -> 8 e's each
    const float4* mrow = (const float4*)(mv_s + n * 68);
    const float4* wbase = (const float4*)(wo_s + egrp * 8 * 64);

    float acc[8];
    #pragma unroll
    for (int j = 0; j < 8; j++) acc[j] = 0.f;

    #pragma unroll 4
    for (int i = 0; i < 16; i++) {
        float4 m = mrow[i];
        #pragma unroll
        for (int j = 0; j < 8; j++) {
            float4 w = wbase[j * 16 + i];
            acc[j] += m.x * w.x + m.y * w.y + m.z * w.z + m.w * w.w;
        }
    }

    float4* outp = (float4*)(g_mvp + ((size_t)b * 64 + n) * 64 + eh + egrp * 8);
    outp[0] = make_float4(acc[0], acc[1], acc[2], acc[3]);
    outp[1] = make_float4(acc[4], acc[5], acc[6], acc[7]);
}

// dirty insert: bubble candidate 'key' through slot K (2 FMNMX)
#define DINS(K) { float t_ = fmaxf((K), key); key = fminf((K), key); (K) = t_; }

// exact bubble level for fallback: incumbent (K,I) vs candidate (sc,si)
#define TOPK_LEVEL(K, I)                                   \
    {                                                      \
        bool  p  = sc > (K);                               \
        float hi = fmaxf((K), sc);                         \
        float lo = fminf((K), sc);                         \
        unsigned ihi = p ? si : (I);                       \
        unsigned ilo = p ? (I) : si;                       \
        (K) = hi; sc = lo; (I) = ihi; si = ilo;            \
    }

// ---------- kernel 1: q-proj + scores + guarded dirty top-8 + softmax ----------
__global__ __launch_bounds__(128, 7)
void score_kernel(const float* __restrict__ x, const float* __restrict__ Wq,
                  const float* __restrict__ maddr)
{
    __shared__ __align__(16) float wq_s[32 * 64];    // [a][d]
    __shared__ __align__(16) float addr_s[64 * 32];  // normalized [n][a]

    const int tid = threadIdx.x;
    const int b   = blockIdx.y;

    {
        const float4* s1 = (const float4*)Wq;
        float4* d1 = (float4*)wq_s;
        #pragma unroll
        for (int i = tid; i < 512; i += 128) d1[i] = s1[i];
    }
    if (tid < 64) {   // normalize address row tid
        const float4* mr = (const float4*)(maddr + tid * 32);
        float4 r[8];
        float ss = 0.f;
        #pragma unroll
        for (int i = 0; i < 8; i++) {
            r[i] = mr[i];
            ss += r[i].x * r[i].x + r[i].y * r[i].y + r[i].z * r[i].z + r[i].w * r[i].w;
        }
        float inv = 1.f / fmaxf(sqrtf(ss), 1e-12f);
        float4* ad = (float4*)(addr_s + tid * 32);
        #pragma unroll
        for (int i = 0; i < 8; i++)
            ad[i] = make_float4(r[i].x * inv, r[i].y * inv, r[i].z * inv, r[i].w * inv);
    }
    __syncthreads();

    const size_t tok = (size_t)b * 8192 + blockIdx.x * 128 + tid;
    const ulonglong2* xr = (const ulonglong2*)(x + tok * 64);

    // ---- q projection, x streamed in quarters ----
    float q[32];
    #pragma unroll
    for (int a = 0; a < 32; a++) q[a] = 0.f;

    for (int h = 0; h < 4; h++) {
        ulonglong2 x0 = xr[h * 4 + 0];
        ulonglong2 x1 = xr[h * 4 + 1];
        ulonglong2 x2 = xr[h * 4 + 2];
        ulonglong2 x3 = xr[h * 4 + 3];
        const ulonglong2* wp = (const ulonglong2*)(wq_s) + h * 4;
        #pragma unroll
        for (int a = 0; a < 32; a++) {
            ulonglong2 w0 = wp[0], w1 = wp[1], w2 = wp[2], w3 = wp[3];
            wp += 16;
            u64 a0 = 0, a1 = 0;
            fma2(a0, x0.x, w0.x); fma2(a1, x0.y, w0.y);
            fma2(a0, x1.x, w1.x); fma2(a1, x1.y, w1.y);
            fma2(a0, x2.x, w2.x); fma2(a1, x2.y, w2.y);
            fma2(a0, x3.x, w3.x); fma2(a1, x3.y, w3.y);
            add2(a0, a1);
            float lo, hi; upk2(a0, lo, hi);
            q[a] += lo + hi;
        }
    }

    u64 qp[16];
    float qq = 0.f;
    #pragma unroll
    for (int i = 0; i < 16; i++) {
        float q0 = q[2 * i], q1 = q[2 * i + 1];
        qq += q0 * q0 + q1 * q1;
        qp[i] = pk2(q0, q1);
    }
    const float scale = 4.f * rsqrtf(fmaxf(qq, 1e-24f));

    // ---- scores + dirty 9-deep top chain (FMNMX only) ----
    float c0 = NEG_INF, c1 = NEG_INF, c2 = NEG_INF, c3 = NEG_INF, c4 = NEG_INF,
          c5 = NEG_INF, c6 = NEG_INF, c7 = NEG_INF, c8 = NEG_INF;

    for (int n = 0; n < 64; n += 2) {
        const ulonglong2* ar = (const ulonglong2*)(addr_s + n * 32);
        u64 a0 = 0, a1 = 0, b0 = 0, b1 = 0;
        #pragma unroll
        for (int i = 0; i < 8; i++) {
            ulonglong2 av = ar[i];
            ulonglong2 bv = ar[i + 8];
            fma2(a0, qp[2 * i],     av.x);
            fma2(a1, qp[2 * i + 1], av.y);
            fma2(b0, qp[2 * i],     bv.x);
            fma2(b1, qp[2 * i + 1], bv.y);
        }
        add2(a0, a1); add2(b0, b1);
        float la, ha, lb, hb;
        upk2(a0, la, ha); upk2(b0, lb, hb);
        float s0 = la + ha, s1 = lb + hb;

        {
            float key = __uint_as_float((__float_as_uint(s0) & 0xFFFFFFC0u) | (unsigned)n);
            DINS(c0); DINS(c1); DINS(c2); DINS(c3); DINS(c4);
            DINS(c5); DINS(c6); DINS(c7); DINS(c8);
        }
        {
            float key = __uint_as_float((__float_as_uint(s1) & 0xFFFFFFC0u) | (unsigned)(n + 1));
            DINS(c0); DINS(c1); DINS(c2); DINS(c3); DINS(c4);
            DINS(c5); DINS(c6); DINS(c7); DINS(c8);
        }
    }

    // ---- exactness guard: boundary bins equal -> exact rescan ----
    float    kk[8] = { c0, c1, c2, c3, c4, c5, c6, c7 };
    unsigned ii[8];

    bool amb = (((__float_as_uint(c7) ^ __float_as_uint(c8)) & 0xFFFFFFC0u) == 0u);
    if (amb) {
        float e0 = NEG_INF, e1 = NEG_INF, e2 = NEG_INF, e3 = NEG_INF;
        float e4 = NEG_INF, e5 = NEG_INF, e6 = NEG_INF, e7 = NEG_INF;
        unsigned j0 = 0, j1 = 0, j2 = 0, j3 = 0, j4 = 0, j5 = 0, j6 = 0, j7 = 0;
        for (int n = 0; n < 64; n++) {
            const ulonglong2* ar = (const ulonglong2*)(addr_s + n * 32);
            u64 a0 = 0, a1 = 0;
            #pragma unroll
            for (int i = 0; i < 8; i++) {
                ulonglong2 av = ar[i];
                fma2(a0, qp[2 * i],     av.x);
                fma2(a1, qp[2 * i + 1], av.y);
            }
            add2(a0, a1);
            float lo, hi; upk2(a0, lo, hi);
            float sc = lo + hi;           // bit-identical to dirty-loop score
            unsigned si = (unsigned)n;
            TOPK_LEVEL(e0, j0); TOPK_LEVEL(e1, j1);
            TOPK_LEVEL(e2, j2); TOPK_LEVEL(e3, j3);
            TOPK_LEVEL(e4, j4); TOPK_LEVEL(e5, j5);
            TOPK_LEVEL(e6, j6); TOPK_LEVEL(e7, j7);
        }
        kk[0] = e0; kk[1] = e1; kk[2] = e2; kk[3] = e3;
        kk[4] = e4; kk[5] = e5; kk[6] = e6; kk[7] = e7;
        ii[0] = j0; ii[1] = j1; ii[2] = j2; ii[3] = j3;
        ii[4] = j4; ii[5] = j5; ii[6] = j6; ii[7] = j7;
    } else {
        #pragma unroll
        for (int j = 0; j < 8; j++) ii[j] = __float_as_uint(kk[j]) & 63u;
    }

    // ---- softmax over top-8 (truncation error <= ~3e-5 on logits) ----
    float ev[8];
    float esum = 0.f;
    #pragma unroll
    for (int j = 0; j < 8; j++) {
        float e = __expf((kk[j] - kk[0]) * scale);
        ev[j] = e;
        esum += e;
    }
    float rinv = 1.0f / esum;

    float p[8];
    #pragma unroll
    for (int j = 0; j < 8; j++) {
        unsigned pu = (__float_as_uint(ev[j] * rinv) & 0xFFFFFFC0u) | ii[j];
        p[j] = __uint_as_float(pu);
    }
    float4* pwout = (float4*)(g_pw + tok * 8);
    pwout[0] = make_float4(p[0], p[1], p[2], p[3]);
    pwout[1] = make_float4(p[4], p[5], p[6], p[7]);
}

// ---------- kernel 2: warp-cooperative gather + coalesced store ----------
__global__ __launch_bounds__(256)
void gather_kernel(float* __restrict__ out)
{
    __shared__ __align__(16) float mvp_s[64 * 64];   // [n][e]
    __shared__ __align__(16) float pw_s[256 * 8];    // staged packed weights

    const int tid  = threadIdx.x;
    const int b    = blockIdx.y;
    const int lane = tid & 31;

    {
        const float4* src = (const float4*)(g_mvp + (size_t)b * 4096);
        float4* dst = (float4*)mvp_s;
        #pragma unroll
        for (int i = tid; i < 1024; i += 256) dst[i] = src[i];
    }

    const int sbase = blockIdx.x * 256;                 // block token base in batch
    const size_t gbase = (size_t)b * 8192 + sbase;
    {
        const float4* psrc = (const float4*)(g_pw + gbase * 8);
        float4* pdst = (float4*)pw_s;
        #pragma unroll
        for (int i = tid; i < 512; i += 256) pdst[i] = psrc[i];
    }
    __syncthreads();

    const float2* mvl = (const float2*)mvp_s + lane;
    const int wtok = tid & ~31;                         // warp's first token (block-local)
    float2* outb = (float2*)(out + (gbase + wtok) * 64);
    const float4* pw4 = (const float4*)(pw_s + wtok * 8);

    for (int t = 0; t < 32; t++) {
        float4 w0 = pw4[t * 2];        // broadcast LDS.128
        float4 w1 = pw4[t * 2 + 1];
        float wv[8] = { w0.x, w0.y, w0.z, w0.w, w1.x, w1.y, w1.z, w1.w };
        float acc0 = 0.f, acc1 = 0.f;
        #pragma unroll
        for (int k = 0; k < 8; k++) {
            unsigned pu = __float_as_uint(wv[k]);
            float2 m = mvl[(pu & 63u) << 5];            // conflict-free
            acc0 += m.x * wv[k];        // low 6 mantissa bits dirty: <=2^-18 rel
            acc1 += m.y * wv[k];
        }
        outb[t * 32 + lane] = make_float2(acc0, acc1);
    }
}

extern "C" void kernel_launch(void* const* d_in, const int* in_sizes, int n_in,
                              void* d_out, int out_size)
{
    const float* x  = (const float*)d_in[0];   // [32,8192,64]
    const float* ma = (const float*)d_in[1];   // [64,32]
    const float* mv = (const float*)d_in[2];   // [32,64,64]
    const float* Wq = (const float*)d_in[3];   // [32,64]
    const float* Wo = (const float*)d_in[4];   // [64,64]
    float* out = (float*)d_out;                // [32,8192,64]

    prep_kernel<<<64, 256>>>(mv, Wo);
    score_kernel<<<dim3(64, 32), 128>>>(x, Wq, ma);
    gather_kernel<<<dim3(32, 32), 256>>>(out);
}